// round 15
// baseline (speedup 1.0000x reference)
#include <cuda_runtime.h>
#include <cuda_bf16.h>
#include <cstdint>

#define MATN  16384
#define BSZ   32
#define SEQ   256
#define CHUNK 16
#define NCH   16

#define NT    256                 // 8 warps; 2 CTAs/SM
#define STRB  272                 // smem row stride bytes (conflict-free ldmatrix)
#define TERM  (128 * STRB)        // 34816 B
#define OFF_AH 0
#define OFF_AM TERM
#define OFF_B  (2 * TERM)
#define SMEM_TOTAL (3 * TERM)     // 104448 B -> 2 CTAs/SM

__device__ __align__(16) float g_T0[(size_t)BSZ * NCH * MATN];
__device__ __align__(16) float g_T1[(size_t)BSZ * NCH * MATN];

// ---------------- PTX helpers ----------------
__device__ __forceinline__ uint32_t smem_u32(const void* p) {
    uint32_t a;
    asm("{ .reg .u64 t; cvta.to.shared.u64 t, %1; cvt.u32.u64 %0, t; }" : "=r"(a) : "l"(p));
    return a;
}
__device__ __forceinline__ void ldsm4(uint32_t* r, uint32_t a) {
    asm volatile("ldmatrix.sync.aligned.m8n8.x4.shared.b16 {%0,%1,%2,%3}, [%4];"
                 : "=r"(r[0]), "=r"(r[1]), "=r"(r[2]), "=r"(r[3]) : "r"(a));
}
__device__ __forceinline__ void ldsm4t(uint32_t* r, uint32_t a) {
    asm volatile("ldmatrix.sync.aligned.m8n8.x4.trans.shared.b16 {%0,%1,%2,%3}, [%4];"
                 : "=r"(r[0]), "=r"(r[1]), "=r"(r[2]), "=r"(r[3]) : "r"(a));
}
__device__ __forceinline__ void mma16816(float* c, const uint32_t* a, const uint32_t* b) {
    asm volatile(
        "mma.sync.aligned.m16n8k16.row.col.f32.bf16.bf16.f32 "
        "{%0,%1,%2,%3}, {%4,%5,%6,%7}, {%8,%9}, {%0,%1,%2,%3};"
        : "+f"(c[0]), "+f"(c[1]), "+f"(c[2]), "+f"(c[3])
        : "r"(a[0]), "r"(a[1]), "r"(a[2]), "r"(a[3]), "r"(b[0]), "r"(b[1]));
}

// packed bf16 split helpers (cvt.rn == __float2bfloat16 rounding)
__device__ __forceinline__ uint32_t cvtH2(float f0, float f1) {
    uint32_t H;
    asm("cvt.rn.bf16x2.f32 %0, %1, %2;" : "=r"(H) : "f"(f1), "f"(f0));
    return H;
}
__device__ __forceinline__ void splitpair(float f0, float f1, uint32_t& H, uint32_t& M) {
    H = cvtH2(f0, f1);
    float r0 = f0 - __uint_as_float(H << 16);
    float r1 = f1 - __uint_as_float(H & 0xffff0000u);
    M = cvtH2(r0, r1);
}

// smem offset for element o (row-major 128x128)
__device__ __forceinline__ int sm_off(int o) { return (o >> 7) * STRB + ((o & 127) << 1); }

// H-term only: global fp32 -> bf16-high tile at OFF_B
__device__ __forceinline__ void split_B_H(const float* __restrict__ G, char* sm, int tid) {
#pragma unroll 4
    for (int it = 0; it < 16; it++) {
        int o = (tid << 2) + (it << 10);
        float4 v = *(const float4*)(G + o);
        uint2 H;
        H.x = cvtH2(v.x, v.y);
        H.y = cvtH2(v.z, v.w);
        *(uint2*)(sm + OFF_B + sm_off(o)) = H;
    }
}
// M-term only (re-derives H to get residual; data is L2-hot)
__device__ __forceinline__ void split_B_M(const float* __restrict__ G, char* sm, int tid) {
#pragma unroll 4
    for (int it = 0; it < 16; it++) {
        int o = (tid << 2) + (it << 10);
        float4 v = *(const float4*)(G + o);
        uint2 H, M;
        splitpair(v.x, v.y, H.x, M.x);
        splitpair(v.z, v.w, H.y, M.y);
        *(uint2*)(sm + OFF_B + sm_off(o)) = M;
    }
}
// A: both terms; optional fp32 mirror copy
__device__ __forceinline__ void split_A(const float* __restrict__ G,
                                        float* __restrict__ mirror, char* sm, int tid) {
#pragma unroll 4
    for (int it = 0; it < 16; it++) {
        int o = (tid << 2) + (it << 10);
        float4 v = *(const float4*)(G + o);
        if (mirror) *(float4*)(mirror + o) = v;
        uint2 H, M;
        splitpair(v.x, v.y, H.x, M.x);
        splitpair(v.z, v.w, H.y, M.y);
        int off = sm_off(o);
        *(uint2*)(sm + OFF_AH + off) = H;
        *(uint2*)(sm + OFF_AM + off) = M;
    }
}

// One matmul step. Pre: OFF_AH/AM hold A terms, OFF_B holds Bh(cur).
// pass1: acc = Ah@Bh + Am@Bh ; swap buffer to Bm ; pass2: acc += Ah@Bm.
// Epilogue: store C to g1/g2, optional A-resplit, load Bh(next) into OFF_B.
__device__ __forceinline__ void cta_step(char* sm, uint32_t smb,
                                         const float* __restrict__ Bcur,
                                         const float* __restrict__ Bnext,
                                         float* __restrict__ g1,
                                         float* __restrict__ g2,
                                         bool resplitA, int tid) {
    const int lane = tid & 31, w = tid >> 5;
    const int mb = (w >> 2) << 6;   // 0/64
    const int nb = (w & 3) << 5;    // 0/32/64/96
    const uint32_t q_lane = (uint32_t)((lane & 15) * STRB + ((lane >> 4) << 4));

    float acc[4][4][4];
#pragma unroll
    for (int mt = 0; mt < 4; mt++)
#pragma unroll
        for (int nt = 0; nt < 4; nt++)
#pragma unroll
            for (int i = 0; i < 4; i++) acc[mt][nt][i] = 0.f;

    // ---- pass 1: hh + mh ----
#pragma unroll
    for (int k0 = 0; k0 < 8; k0++) {
        const int kk = k0 << 4;
        uint32_t ah[4][4], am[4][4], bh[2][4];
#pragma unroll
        for (int mt = 0; mt < 4; mt++) {
            uint32_t base = smb + (uint32_t)((mb + mt * 16) * STRB + (kk << 1)) + q_lane;
            ldsm4(ah[mt], base + OFF_AH);
            ldsm4(am[mt], base + OFF_AM);
        }
#pragma unroll
        for (int p = 0; p < 2; p++)
            ldsm4t(bh[p], smb + OFF_B + (uint32_t)(kk * STRB + ((nb + p * 16) << 1)) + q_lane);
#pragma unroll
        for (int mt = 0; mt < 4; mt++)
#pragma unroll
            for (int nt = 0; nt < 4; nt++)
                mma16816(acc[mt][nt], ah[mt], &bh[nt >> 1][(nt & 1) << 1]);
#pragma unroll
        for (int mt = 0; mt < 4; mt++)
#pragma unroll
            for (int nt = 0; nt < 4; nt++)
                mma16816(acc[mt][nt], am[mt], &bh[nt >> 1][(nt & 1) << 1]);
    }

    __syncthreads();                 // Bh reads done
    split_B_M(Bcur, sm, tid);        // buffer := Bm (L2-hot re-load)
    __syncthreads();                 // Bm visible

    // ---- pass 2: hm ----
#pragma unroll
    for (int k0 = 0; k0 < 8; k0++) {
        const int kk = k0 << 4;
        uint32_t ah[4][4], bm[2][4];
#pragma unroll
        for (int mt = 0; mt < 4; mt++)
            ldsm4(ah[mt], smb + OFF_AH + (uint32_t)((mb + mt * 16) * STRB + (kk << 1)) + q_lane);
#pragma unroll
        for (int p = 0; p < 2; p++)
            ldsm4t(bm[p], smb + OFF_B + (uint32_t)(kk * STRB + ((nb + p * 16) << 1)) + q_lane);
#pragma unroll
        for (int mt = 0; mt < 4; mt++)
#pragma unroll
            for (int nt = 0; nt < 4; nt++)
                mma16816(acc[mt][nt], ah[mt], &bm[nt >> 1][(nt & 1) << 1]);
    }

    __syncthreads();                 // Bm / A reads done

    // ---- epilogue ----
    const int r_off = lane >> 2;
    const int c_off = (lane & 3) << 1;
#pragma unroll
    for (int mt = 0; mt < 4; mt++) {
#pragma unroll
        for (int nt = 0; nt < 4; nt++) {
            int row0 = mb + mt * 16 + r_off;
            int col  = nb + nt * 8 + c_off;
#pragma unroll
            for (int half = 0; half < 2; half++) {
                int row = row0 + half * 8;
                float vx = acc[mt][nt][2 * half];
                float vy = acc[mt][nt][2 * half + 1];
                if (g1) *(float2*)(g1 + ((size_t)row << 7) + col) = make_float2(vx, vy);
                if (g2) *(float2*)(g2 + ((size_t)row << 7) + col) = make_float2(vx, vy);
                if (resplitA) {
                    uint32_t Hw, Mw;
                    splitpair(vx, vy, Hw, Mw);
                    int off = row * STRB + (col << 1);
                    *(uint32_t*)(sm + OFF_AH + off) = Hw;
                    *(uint32_t*)(sm + OFF_AM + off) = Mw;
                }
            }
        }
    }
    if (Bnext) split_B_H(Bnext, sm, tid);   // buffer := Bh(next)
    __syncthreads();
}

// ---------------- kernels ----------------

__global__ void __launch_bounds__(NT, 2) k_phase1(const float* __restrict__ in,
                                                  float* __restrict__ ao) {
    extern __shared__ char sm[];
    uint32_t smb = smem_u32(sm);
    int tid = threadIdx.x;
    int b = blockIdx.x >> 4, c = blockIdx.x & 15;
    const float* A0 = in + (size_t)(b * SEQ + c * CHUNK) * MATN;
    float* out0 = ao + (size_t)(b * SEQ + c * CHUNK) * MATN;

    split_A(A0, out0, sm, tid);      // prefix[0] = A0, mirrored out
    split_B_H(A0 + MATN, sm, tid);   // Bh(first)
    __syncthreads();
    for (int s = 1; s < CHUNK; s++) {
        bool last = (s == CHUNK - 1);
        cta_step(sm, smb,
                 A0 + (size_t)s * MATN,
                 last ? nullptr : (A0 + (size_t)(s + 1) * MATN),
                 out0 + (size_t)s * MATN,
                 last ? (g_T0 + (size_t)(b * NCH + c) * MATN) : nullptr,
                 !last, tid);
    }
}

__global__ void __launch_bounds__(NT, 2) k_scan(int dlev, int dir) {
    float* src = dir ? g_T1 : g_T0;
    float* dst = dir ? g_T0 : g_T1;
    int b = blockIdx.x >> 4, c = blockIdx.x & 15;
    int tid = threadIdx.x;
    size_t idx = (size_t)(b * NCH + c) * MATN;
    if (c < dlev) {
        for (int o = tid << 2; o < MATN; o += (NT * 4))
            *(float4*)(dst + idx + o) = *(const float4*)(src + idx + o);
        return;
    }
    extern __shared__ char sm[];
    uint32_t smb = smem_u32(sm);
    split_A(src + (size_t)(b * NCH + (c - dlev)) * MATN, nullptr, sm, tid);
    split_B_H(src + idx, sm, tid);
    __syncthreads();
    cta_step(sm, smb, src + idx, nullptr, dst + idx, nullptr, false, tid);
}

// apply + fused x-write. Scan result (4 levels T0->T1->T0->T1->T0) lives in g_T0.
__global__ void __launch_bounds__(NT, 2) k_apply(float* __restrict__ ao,
                                                 float* __restrict__ xout) {
    extern __shared__ char sm[];
    uint32_t smb = smem_u32(sm);
    int tid = threadIdx.x;
    int blk = blockIdx.x;
    int b = blk / 30;
    int rem = blk % 30;
    int c = (rem >> 1) + 1;   // chunk 1..15
    int q = rem & 1;          // half of the chunk (8 matmuls each)
    int t0 = c * CHUNK + q * 8;
    float* L0 = ao + (size_t)(b * SEQ + t0) * MATN;
    bool isLastCTA = (c == NCH - 1) && (q == 1);

    split_A(g_T0 + (size_t)(b * NCH + (c - 1)) * MATN, nullptr, sm, tid);
    split_B_H(L0, sm, tid);
    __syncthreads();
    for (int u = 0; u < 8; u++) {
        float* g2 = (xout && isLastCTA && u == 7) ? (xout + (size_t)b * MATN) : nullptr;
        cta_step(sm, smb,
                 L0 + (size_t)u * MATN,
                 (u < 7) ? (L0 + (size_t)(u + 1) * MATN) : nullptr,
                 L0 + (size_t)u * MATN, g2, false, tid);
    }
}

extern "C" void kernel_launch(void* const* d_in, const int* in_sizes, int n_in,
                              void* d_out, int out_size) {
    const float* in = (const float*)d_in[0];
    float* out = (float*)d_out;
    const size_t AO = (size_t)BSZ * SEQ * MATN;
    const size_t XN = (size_t)BSZ * MATN;

    float* x = nullptr;
    float* ao = out;
    if ((size_t)out_size >= AO + XN) { x = out; ao = out + XN; }

    cudaFuncSetAttribute(k_phase1, cudaFuncAttributeMaxDynamicSharedMemorySize, SMEM_TOTAL);
    cudaFuncSetAttribute(k_scan,   cudaFuncAttributeMaxDynamicSharedMemorySize, SMEM_TOTAL);
    cudaFuncSetAttribute(k_apply,  cudaFuncAttributeMaxDynamicSharedMemorySize, SMEM_TOTAL);

    k_phase1<<<BSZ * NCH, NT, SMEM_TOTAL>>>(in, ao);
    k_scan<<<BSZ * NCH, NT, SMEM_TOTAL>>>(1, 0);   // T0 -> T1
    k_scan<<<BSZ * NCH, NT, SMEM_TOTAL>>>(2, 1);   // T1 -> T0
    k_scan<<<BSZ * NCH, NT, SMEM_TOTAL>>>(4, 0);   // T0 -> T1
    k_scan<<<BSZ * NCH, NT, SMEM_TOTAL>>>(8, 1);   // T1 -> T0 (final in T0)
    k_apply<<<BSZ * 15 * 2, NT, SMEM_TOTAL>>>(ao, x);
}

// round 16
// speedup vs baseline: 1.0083x; 1.0083x over previous
#include <cuda_runtime.h>
#include <cuda_bf16.h>
#include <cstdint>

#define MATN  16384
#define BSZ   32
#define SEQ   256
#define CHUNK 64
#define NCH   4

#define NT    512                 // threads per CTA (16 warps)
#define STRB  272                 // smem row stride bytes (conflict-free ldmatrix)
#define TERM  (128 * STRB)        // 34816 B
#define OFF_AH 0
#define OFF_AM TERM
// B term tiles, double buffered: BH(buf) = (2+2*buf)*TERM, BM(buf) = (3+2*buf)*TERM
#define SMEM_TOTAL (6 * TERM)     // 208896 B

__device__ __align__(16) float g_T0[(size_t)BSZ * NCH * MATN];
__device__ __align__(16) float g_T1[(size_t)BSZ * NCH * MATN];

// ---------------- PTX helpers ----------------
__device__ __forceinline__ uint32_t smem_u32(const void* p) {
    uint32_t a;
    asm("{ .reg .u64 t; cvta.to.shared.u64 t, %1; cvt.u32.u64 %0, t; }" : "=r"(a) : "l"(p));
    return a;
}
__device__ __forceinline__ void ldsm4(uint32_t* r, uint32_t a) {
    asm volatile("ldmatrix.sync.aligned.m8n8.x4.shared.b16 {%0,%1,%2,%3}, [%4];"
                 : "=r"(r[0]), "=r"(r[1]), "=r"(r[2]), "=r"(r[3]) : "r"(a));
}
__device__ __forceinline__ void ldsm4t(uint32_t* r, uint32_t a) {
    asm volatile("ldmatrix.sync.aligned.m8n8.x4.trans.shared.b16 {%0,%1,%2,%3}, [%4];"
                 : "=r"(r[0]), "=r"(r[1]), "=r"(r[2]), "=r"(r[3]) : "r"(a));
}
__device__ __forceinline__ void mma16816(float* c, const uint32_t* a, const uint32_t* b) {
    asm volatile(
        "mma.sync.aligned.m16n8k16.row.col.f32.bf16.bf16.f32 "
        "{%0,%1,%2,%3}, {%4,%5,%6,%7}, {%8,%9}, {%0,%1,%2,%3};"
        : "+f"(c[0]), "+f"(c[1]), "+f"(c[2]), "+f"(c[3])
        : "r"(a[0]), "r"(a[1]), "r"(a[2]), "r"(a[3]), "r"(b[0]), "r"(b[1]));
}

// packed bf16 split (cvt.rn == __float2bfloat16 rounding)
__device__ __forceinline__ uint32_t cvtH2(float f0, float f1) {
    uint32_t H;
    asm("cvt.rn.bf16x2.f32 %0, %1, %2;" : "=r"(H) : "f"(f1), "f"(f0));
    return H;
}
__device__ __forceinline__ void splitpair(float f0, float f1, uint32_t& H, uint32_t& M) {
    H = cvtH2(f0, f1);
    float r0 = f0 - __uint_as_float(H << 16);
    float r1 = f1 - __uint_as_float(H & 0xffff0000u);
    M = cvtH2(r0, r1);
}
__device__ __forceinline__ void split4(float4 v, uint2& H, uint2& M) {
    splitpair(v.x, v.y, H.x, M.x);
    splitpair(v.z, v.w, H.y, M.y);
}
__device__ __forceinline__ int sm_off(int o) { return (o >> 7) * STRB + ((o & 127) << 1); }

// Full split of a global fp32 128x128 into term tiles at offH/offM. NT threads.
__device__ __forceinline__ void split_full(const float* __restrict__ G,
                                           float* __restrict__ mirror,
                                           char* sm, int offH, int offM, int tid) {
#pragma unroll 4
    for (int it = 0; it < 8; it++) {
        int o = (tid << 2) + (it << 11);
        float4 v = *(const float4*)(G + o);
        if (mirror) *(float4*)(mirror + o) = v;
        uint2 H, M; split4(v, H, M);
        int off = sm_off(o);
        *(uint2*)(sm + offH + off) = H;
        *(uint2*)(sm + offM + off) = M;
    }
}

// 128x128x128 matmul step. B terms double-buffered; reads buf, and while the
// k-loop runs, loads+splits nextB directly from GMEM into buf^1 (one float4
// per thread per k-iteration; LDG hidden under the MMA work of the iteration).
// Pass-reordered MMAs; fragment double buffering; epilogue = C stores + optional
// A resplit only.
__device__ __forceinline__ void cta_mm(char* sm, uint32_t smb, int buf,
                                       const float* __restrict__ nextB,
                                       float* __restrict__ g1,
                                       float* __restrict__ g2,
                                       bool resplitA, int tid) {
    const int lane = tid & 31, w = tid >> 5;
    const int mb = (w >> 2) << 5;   // 0/32/64/96
    const int nb = (w & 3) << 5;    // 0/32/64/96
    const uint32_t q_lane = (uint32_t)((lane & 15) * STRB + ((lane >> 4) << 4));

    const uint32_t OFF_BHc = (uint32_t)((2 + 2 * buf) * TERM);
    const uint32_t OFF_BMc = OFF_BHc + TERM;
    const int OFF_BHn = (2 + 2 * (buf ^ 1)) * TERM;
    const int OFF_BMn = OFF_BHn + TERM;

    float acc[2][4][4];
#pragma unroll
    for (int mt = 0; mt < 2; mt++)
#pragma unroll
        for (int nt = 0; nt < 4; nt++)
#pragma unroll
            for (int i = 0; i < 4; i++) acc[mt][nt][i] = 0.f;

    uint32_t ah[2][2][4], am[2][2][4];   // [fbuf][mt][reg]
    uint32_t bh[2][2][4], bm[2][2][4];   // [fbuf][pair][reg]

    // load k0 = 0 fragments
#pragma unroll
    for (int mt = 0; mt < 2; mt++) {
        uint32_t base = smb + (uint32_t)((mb + mt * 16) * STRB) + q_lane;
        ldsm4(ah[0][mt], base + OFF_AH);
        ldsm4(am[0][mt], base + OFF_AM);
    }
#pragma unroll
    for (int p = 0; p < 2; p++) {
        uint32_t base = smb + (uint32_t)((nb + p * 16) << 1) + q_lane;
        ldsm4t(bh[0][p], base + OFF_BHc);
        ldsm4t(bm[0][p], base + OFF_BMc);
    }

#pragma unroll
    for (int k0 = 0; k0 < 8; k0++) {
        const int cur = k0 & 1, nxt = cur ^ 1;

        // next-B chunk: issue LDG at iteration top (consumed after the MMAs)
        float4 nv;
        int no = 0;
        if (nextB) {
            no = (tid << 2) + (k0 << 11);
            nv = *(const float4*)(nextB + no);
        }

        if (k0 < 7) {   // prefetch k0+1 fragments before consuming k0
            const int kk = (k0 + 1) << 4;
#pragma unroll
            for (int mt = 0; mt < 2; mt++) {
                uint32_t base = smb + (uint32_t)((mb + mt * 16) * STRB + (kk << 1)) + q_lane;
                ldsm4(ah[nxt][mt], base + OFF_AH);
                ldsm4(am[nxt][mt], base + OFF_AM);
            }
#pragma unroll
            for (int p = 0; p < 2; p++) {
                uint32_t base = smb + (uint32_t)(kk * STRB + ((nb + p * 16) << 1)) + q_lane;
                ldsm4t(bh[nxt][p], base + OFF_BHc);
                ldsm4t(bm[nxt][p], base + OFF_BMc);
            }
        }
        // pass 1: hh
#pragma unroll
        for (int mt = 0; mt < 2; mt++)
#pragma unroll
            for (int nt = 0; nt < 4; nt++)
                mma16816(acc[mt][nt], ah[cur][mt], &bh[cur][nt >> 1][(nt & 1) << 1]);
        // pass 2: hm
#pragma unroll
        for (int mt = 0; mt < 2; mt++)
#pragma unroll
            for (int nt = 0; nt < 4; nt++)
                mma16816(acc[mt][nt], ah[cur][mt], &bm[cur][nt >> 1][(nt & 1) << 1]);
        // pass 3: mh
#pragma unroll
        for (int mt = 0; mt < 2; mt++)
#pragma unroll
            for (int nt = 0; nt < 4; nt++)
                mma16816(acc[mt][nt], am[cur][mt], &bh[cur][nt >> 1][(nt & 1) << 1]);

        // split the prefetched next-B chunk into buf^1 (no WAR with cur buffer)
        if (nextB) {
            uint2 H, M; split4(nv, H, M);
            int off = sm_off(no);
            *(uint2*)(sm + OFF_BHn + off) = H;
            *(uint2*)(sm + OFF_BMn + off) = M;
        }
    }

    __syncthreads();   // A (and B) smem reads done before any overwrite below

    const int r_off = lane >> 2;
    const int c_off = (lane & 3) << 1;
#pragma unroll
    for (int mt = 0; mt < 2; mt++) {
#pragma unroll
        for (int nt = 0; nt < 4; nt++) {
            int row0 = mb + mt * 16 + r_off;
            int col  = nb + nt * 8 + c_off;
#pragma unroll
            for (int half = 0; half < 2; half++) {
                int row = row0 + half * 8;
                float vx = acc[mt][nt][2 * half];
                float vy = acc[mt][nt][2 * half + 1];
                if (g1) *(float2*)(g1 + ((size_t)row << 7) + col) = make_float2(vx, vy);
                if (g2) *(float2*)(g2 + ((size_t)row << 7) + col) = make_float2(vx, vy);
                if (resplitA) {
                    uint32_t Hw, Mw;
                    splitpair(vx, vy, Hw, Mw);   // packed h0|h1<<16 directly
                    int off = row * STRB + (col << 1);
                    *(uint32_t*)(sm + OFF_AH + off) = Hw;
                    *(uint32_t*)(sm + OFF_AM + off) = Mw;
                }
            }
        }
    }
    __syncthreads();   // new A tile (and buf^1 B tiles) visible before next step
}

// ---------------- kernels ----------------

__global__ void __launch_bounds__(NT, 1) k_phase1(const float* __restrict__ in,
                                                  float* __restrict__ ao) {
    extern __shared__ char sm[];
    uint32_t smb = smem_u32(sm);
    int tid = threadIdx.x;
    int b = blockIdx.x >> 2, c = blockIdx.x & 3;
    const float* A0 = in + (size_t)(b * SEQ + c * CHUNK) * MATN;
    float* out0 = ao + (size_t)(b * SEQ + c * CHUNK) * MATN;

    split_full(A0, out0, sm, OFF_AH, OFF_AM, tid);              // prefix[0] = A0
    split_full(A0 + MATN, nullptr, sm, 2 * TERM, 3 * TERM, tid); // B(first) -> buf 0
    __syncthreads();
    int buf = 0;
    for (int s = 1; s < CHUNK; s++) {
        bool last = (s == CHUNK - 1);
        cta_mm(sm, smb, buf,
               last ? nullptr : (A0 + (size_t)(s + 1) * MATN),
               out0 + (size_t)s * MATN,
               last ? (g_T0 + (size_t)(b * NCH + c) * MATN) : nullptr,
               !last, tid);
        buf ^= 1;
    }
}

__global__ void __launch_bounds__(NT, 1) k_scan(int dlev, int dir) {
    float* src = dir ? g_T1 : g_T0;
    float* dst = dir ? g_T0 : g_T1;
    int b = blockIdx.x >> 2, c = blockIdx.x & 3;
    int tid = threadIdx.x;
    size_t idx = (size_t)(b * NCH + c) * MATN;
    if (c < dlev) {
        for (int o = tid << 2; o < MATN; o += (NT * 4))
            *(float4*)(dst + idx + o) = *(const float4*)(src + idx + o);
        return;
    }
    extern __shared__ char sm[];
    uint32_t smb = smem_u32(sm);
    split_full(src + (size_t)(b * NCH + (c - dlev)) * MATN, nullptr, sm, OFF_AH, OFF_AM, tid);
    split_full(src + idx, nullptr, sm, 2 * TERM, 3 * TERM, tid);
    __syncthreads();
    cta_mm(sm, smb, 0, nullptr, dst + idx, nullptr, false, tid);
}

// apply + fused x-write. Scan result (2 levels: T0->T1->T0) lives in g_T0.
// 16 matmuls per CTA: 384 CTAs = 32 batches x 12.
__global__ void __launch_bounds__(NT, 1) k_apply(float* __restrict__ ao,
                                                 float* __restrict__ xout) {
    extern __shared__ char sm[];
    uint32_t smb = smem_u32(sm);
    int tid = threadIdx.x;
    int blk = blockIdx.x;
    int b = blk / 12;
    int rem = blk % 12;
    int c = (rem >> 2) + 1;   // chunk 1..3
    int q = rem & 3;          // quarter of the chunk (16 matmuls each)
    int t0 = c * CHUNK + q * 16;
    float* L0 = ao + (size_t)(b * SEQ + t0) * MATN;
    bool isLastCTA = (c == NCH - 1) && (q == 3);

    split_full(g_T0 + (size_t)(b * NCH + (c - 1)) * MATN, nullptr, sm, OFF_AH, OFF_AM, tid);
    split_full(L0, nullptr, sm, 2 * TERM, 3 * TERM, tid);
    __syncthreads();
    int buf = 0;
    for (int u = 0; u < 16; u++) {
        float* g2 = (xout && isLastCTA && u == 15) ? (xout + (size_t)b * MATN) : nullptr;
        cta_mm(sm, smb, buf,
               (u < 15) ? (L0 + (size_t)(u + 1) * MATN) : nullptr,
               L0 + (size_t)u * MATN, g2, false, tid);
        buf ^= 1;
    }
}

extern "C" void kernel_launch(void* const* d_in, const int* in_sizes, int n_in,
                              void* d_out, int out_size) {
    const float* in = (const float*)d_in[0];
    float* out = (float*)d_out;
    const size_t AO = (size_t)BSZ * SEQ * MATN;
    const size_t XN = (size_t)BSZ * MATN;

    float* x = nullptr;
    float* ao = out;
    if ((size_t)out_size >= AO + XN) { x = out; ao = out + XN; }

    cudaFuncSetAttribute(k_phase1, cudaFuncAttributeMaxDynamicSharedMemorySize, SMEM_TOTAL);
    cudaFuncSetAttribute(k_scan,   cudaFuncAttributeMaxDynamicSharedMemorySize, SMEM_TOTAL);
    cudaFuncSetAttribute(k_apply,  cudaFuncAttributeMaxDynamicSharedMemorySize, SMEM_TOTAL);

    k_phase1<<<BSZ * NCH, NT, SMEM_TOTAL>>>(in, ao);
    k_scan<<<BSZ * NCH, NT, SMEM_TOTAL>>>(1, 0);   // T0 -> T1
    k_scan<<<BSZ * NCH, NT, SMEM_TOTAL>>>(2, 1);   // T1 -> T0 (final in T0)
    k_apply<<<BSZ * 12, NT, SMEM_TOTAL>>>(ao, x);
}